// round 2
// baseline (speedup 1.0000x reference)
#include <cuda_runtime.h>
#include <math.h>

#define B_  8
#define T_  1024
#define E_  1024
#define H_  16
#define DH_ 64

// Scratch (allocation-free rule: __device__ globals, referenced directly
// from device code — no runtime API calls needed in kernel_launch)
__device__ float g_qkv[(size_t)B_ * T_ * 3 * E_];  // 96 MB
__device__ float g_att[(size_t)B_ * T_ * E_];      // 32 MB
__device__ float g_p1 [(size_t)B_ * T_ * E_];      // 32 MB

// ---------------------------------------------------------------------------
// C[M,N] = A[M,K] @ B[N,K]^T + bias[N]   (A, B row-major, K contiguous)
// 128x128 block tile, BK=16, 256 threads, 8x8 per-thread micro-tile.
// All dims divide tile sizes exactly for this problem (no bounds checks).
// ---------------------------------------------------------------------------
__global__ void __launch_bounds__(256) gemm_nt_bias(
    const float* __restrict__ A, const float* __restrict__ Bm,
    const float* __restrict__ bias, float* __restrict__ C,
    int M, int N, int K)
{
    constexpr int BK = 16;
    __shared__ float As[BK][132];
    __shared__ float Bs[BK][132];

    const int tid = threadIdx.x;
    const int bm  = blockIdx.y * 128;
    const int bn  = blockIdx.x * 128;
    const int tx  = tid & 15;   // N direction
    const int ty  = tid >> 4;   // M direction

    float acc[8][8];
#pragma unroll
    for (int i = 0; i < 8; i++)
#pragma unroll
        for (int j = 0; j < 8; j++) acc[i][j] = 0.f;

    for (int k0 = 0; k0 < K; k0 += BK) {
#pragma unroll
        for (int i = 0; i < 2; i++) {
            int idx = tid + i * 256;          // 0..511
            int row = idx >> 2;               // 0..127
            int k4  = (idx & 3) << 2;         // 0,4,8,12
            float4 v = *reinterpret_cast<const float4*>(
                A + (size_t)(bm + row) * K + k0 + k4);
            As[k4 + 0][row] = v.x; As[k4 + 1][row] = v.y;
            As[k4 + 2][row] = v.z; As[k4 + 3][row] = v.w;
        }
#pragma unroll
        for (int i = 0; i < 2; i++) {
            int idx = tid + i * 256;
            int row = idx >> 2;
            int k4  = (idx & 3) << 2;
            float4 v = *reinterpret_cast<const float4*>(
                Bm + (size_t)(bn + row) * K + k0 + k4);
            Bs[k4 + 0][row] = v.x; Bs[k4 + 1][row] = v.y;
            Bs[k4 + 2][row] = v.z; Bs[k4 + 3][row] = v.w;
        }
        __syncthreads();

#pragma unroll
        for (int k = 0; k < BK; k++) {
            float ra[8], rb[8];
            *reinterpret_cast<float4*>(ra)     = *reinterpret_cast<const float4*>(&As[k][ty * 8]);
            *reinterpret_cast<float4*>(ra + 4) = *reinterpret_cast<const float4*>(&As[k][ty * 8 + 4]);
            *reinterpret_cast<float4*>(rb)     = *reinterpret_cast<const float4*>(&Bs[k][tx * 8]);
            *reinterpret_cast<float4*>(rb + 4) = *reinterpret_cast<const float4*>(&Bs[k][tx * 8 + 4]);
#pragma unroll
            for (int i = 0; i < 8; i++)
#pragma unroll
                for (int j = 0; j < 8; j++)
                    acc[i][j] = fmaf(ra[i], rb[j], acc[i][j]);
        }
        __syncthreads();
    }

    float bv[8];
#pragma unroll
    for (int j = 0; j < 8; j++) bv[j] = bias[bn + tx * 8 + j];

#pragma unroll
    for (int i = 0; i < 8; i++) {
        size_t off = (size_t)(bm + ty * 8 + i) * N + bn + tx * 8;
        float4 o0 = make_float4(acc[i][0] + bv[0], acc[i][1] + bv[1],
                                acc[i][2] + bv[2], acc[i][3] + bv[3]);
        float4 o1 = make_float4(acc[i][4] + bv[4], acc[i][5] + bv[5],
                                acc[i][6] + bv[6], acc[i][7] + bv[7]);
        *reinterpret_cast<float4*>(C + off)     = o0;
        *reinterpret_cast<float4*>(C + off + 4) = o1;
    }
}

// Thin wrappers binding scratch symbols (avoids any runtime symbol lookup)
__global__ void __launch_bounds__(256) gemm_qkv(
    const float* __restrict__ A, const float* __restrict__ W,
    const float* __restrict__ bias)
{
    // delegate by inlining the body via a device call is overkill; instead we
    // just call the generic kernel's logic through a launch in host code with
    // direct symbol pointers — handled below with dedicated kernels.
}

// ---------------------------------------------------------------------------
// Causal flash attention, fp32.
// grid: (T/64, B*H). 256 threads. 64 query rows per CTA, KV tiles of 32.
// Reads g_qkv directly, writes g_att in [B, T, E] layout (transpose fused).
// ---------------------------------------------------------------------------
__global__ void __launch_bounds__(256) flash_attn()
{
    __shared__ float Qs[64][68];  // [d][query row]
    __shared__ float Ks[64][36];  // [d][key]
    __shared__ float Vs[32][68];  // [key][d]
    __shared__ float Ps[32][68];  // [key][query row]

    const float* qkv = g_qkv;
    float* out = g_att;

    const int tid = threadIdx.x;
    const int tx  = tid & 15;    // S-cols (x2) / O d-cols (x4)
    const int ty  = tid >> 4;    // rows (x4)
    const int qb  = blockIdx.x;
    const int b   = blockIdx.y >> 4;
    const int h   = blockIdx.y & 15;
    const size_t base = (size_t)b * T_ * 3 * E_ + (size_t)h * DH_;

    // Load 64x64 Q tile, transposed into Qs[d][row]
#pragma unroll
    for (int i = 0; i < 4; i++) {
        int idx = tid + i * 256;         // 0..1023
        int row = idx >> 4;              // 0..63
        int d4  = (idx & 15) << 2;       // 0..60
        float4 v = *reinterpret_cast<const float4*>(
            qkv + base + (size_t)(qb * 64 + row) * 3 * E_ + d4);
        Qs[d4 + 0][row] = v.x; Qs[d4 + 1][row] = v.y;
        Qs[d4 + 2][row] = v.z; Qs[d4 + 3][row] = v.w;
    }

    float m[4], l[4], o[4][4];
#pragma unroll
    for (int i = 0; i < 4; i++) {
        m[i] = -INFINITY; l[i] = 0.f;
#pragma unroll
        for (int j = 0; j < 4; j++) o[i][j] = 0.f;
    }

    const int nkb = 2 * qb + 2;   // causal: KV blocks 0 .. 2qb+1
    for (int kb = 0; kb < nkb; kb++) {
        __syncthreads();   // previous iteration done reading Ks/Vs/Ps

        // Load K (transposed) and V tiles: 32 keys x 64 d
#pragma unroll
        for (int i = 0; i < 2; i++) {
            int idx = tid + i * 256;     // 0..511
            int row = idx >> 4;          // key 0..31
            int d4  = (idx & 15) << 2;
            size_t tok = (size_t)(kb * 32 + row) * 3 * E_;
            float4 kv4 = *reinterpret_cast<const float4*>(qkv + base + E_ + tok + d4);
            Ks[d4 + 0][row] = kv4.x; Ks[d4 + 1][row] = kv4.y;
            Ks[d4 + 2][row] = kv4.z; Ks[d4 + 3][row] = kv4.w;
            *reinterpret_cast<float4*>(&Vs[row][d4]) =
                *reinterpret_cast<const float4*>(qkv + base + 2 * E_ + tok + d4);
        }
        __syncthreads();

        // S = Q K^T : rows ty*4..+3, cols tx*2..+1
        float s[4][2] = {};
#pragma unroll 16
        for (int d = 0; d < 64; d++) {
            float4 qa = *reinterpret_cast<const float4*>(&Qs[d][ty * 4]);
            float k0 = Ks[d][tx * 2], k1 = Ks[d][tx * 2 + 1];
            s[0][0] = fmaf(qa.x, k0, s[0][0]); s[0][1] = fmaf(qa.x, k1, s[0][1]);
            s[1][0] = fmaf(qa.y, k0, s[1][0]); s[1][1] = fmaf(qa.y, k1, s[1][1]);
            s[2][0] = fmaf(qa.z, k0, s[2][0]); s[2][1] = fmaf(qa.z, k1, s[2][1]);
            s[3][0] = fmaf(qa.w, k0, s[3][0]); s[3][1] = fmaf(qa.w, k1, s[3][1]);
        }

        const bool need_mask = (kb >= 2 * qb);
#pragma unroll
        for (int i = 0; i < 4; i++)
#pragma unroll
            for (int j = 0; j < 2; j++) {
                float sv = s[i][j] * 0.125f;  // 1/sqrt(64)
                if (need_mask) {
                    int rg = qb * 64 + ty * 4 + i;
                    int cg = kb * 32 + tx * 2 + j;
                    if (cg > rg) sv = -1e30f;
                }
                s[i][j] = sv;
            }

        // Online softmax, row stats reduced over the 16 tx lanes
#pragma unroll
        for (int i = 0; i < 4; i++) {
            float rm = fmaxf(s[i][0], s[i][1]);
#pragma unroll
            for (int ofs = 8; ofs > 0; ofs >>= 1)
                rm = fmaxf(rm, __shfl_xor_sync(0xffffffffu, rm, ofs));
            float mn = fmaxf(m[i], rm);
            float alpha = __expf(m[i] - mn);
            m[i] = mn;
            float p0 = __expf(s[i][0] - mn);
            float p1 = __expf(s[i][1] - mn);
            float rs = p0 + p1;
#pragma unroll
            for (int ofs = 8; ofs > 0; ofs >>= 1)
                rs += __shfl_xor_sync(0xffffffffu, rs, ofs);
            l[i] = l[i] * alpha + rs;
#pragma unroll
            for (int j = 0; j < 4; j++) o[i][j] *= alpha;
            Ps[tx * 2 + 0][ty * 4 + i] = p0;
            Ps[tx * 2 + 1][ty * 4 + i] = p1;
        }
        __syncthreads();

        // O += P @ V : rows ty*4..+3, d-cols tx*4..+3
#pragma unroll 8
        for (int c = 0; c < 32; c++) {
            float4 vv = *reinterpret_cast<const float4*>(&Vs[c][tx * 4]);
#pragma unroll
            for (int i = 0; i < 4; i++) {
                float p = Ps[c][ty * 4 + i];
                o[i][0] = fmaf(p, vv.x, o[i][0]);
                o[i][1] = fmaf(p, vv.y, o[i][1]);
                o[i][2] = fmaf(p, vv.z, o[i][2]);
                o[i][3] = fmaf(p, vv.w, o[i][3]);
            }
        }
    }

    // Normalize and write out in [B, T, E] layout (head-transpose fused)
#pragma unroll
    for (int i = 0; i < 4; i++) {
        float inv = 1.f / l[i];
        size_t off = ((size_t)b * T_ + qb * 64 + ty * 4 + i) * E_ + h * DH_ + tx * 4;
        float4 ov = make_float4(o[i][0] * inv, o[i][1] * inv,
                                o[i][2] * inv, o[i][3] * inv);
        *reinterpret_cast<float4*>(out + off) = ov;
    }
}

// ---------------------------------------------------------------------------
// Dedicated GEMM entry points that bind the scratch symbols on the device
// side, so kernel_launch needs zero runtime API calls besides launches.
// ---------------------------------------------------------------------------
__device__ __forceinline__ void gemm_body(
    const float* __restrict__ A, const float* __restrict__ Bm,
    const float* __restrict__ bias, float* __restrict__ C,
    int M, int N, int K)
{
    constexpr int BK = 16;
    __shared__ float As[BK][132];
    __shared__ float Bs[BK][132];

    const int tid = threadIdx.x;
    const int bm  = blockIdx.y * 128;
    const int bn  = blockIdx.x * 128;
    const int tx  = tid & 15;
    const int ty  = tid >> 4;

    float acc[8][8];
#pragma unroll
    for (int i = 0; i < 8; i++)
#pragma unroll
        for (int j = 0; j < 8; j++) acc[i][j] = 0.f;

    for (int k0 = 0; k0 < K; k0 += BK) {
#pragma unroll
        for (int i = 0; i < 2; i++) {
            int idx = tid + i * 256;
            int row = idx >> 2;
            int k4  = (idx & 3) << 2;
            float4 v = *reinterpret_cast<const float4*>(
                A + (size_t)(bm + row) * K + k0 + k4);
            As[k4 + 0][row] = v.x; As[k4 + 1][row] = v.y;
            As[k4 + 2][row] = v.z; As[k4 + 3][row] = v.w;
        }
#pragma unroll
        for (int i = 0; i < 2; i++) {
            int idx = tid + i * 256;
            int row = idx >> 2;
            int k4  = (idx & 3) << 2;
            float4 v = *reinterpret_cast<const float4*>(
                Bm + (size_t)(bn + row) * K + k0 + k4);
            Bs[k4 + 0][row] = v.x; Bs[k4 + 1][row] = v.y;
            Bs[k4 + 2][row] = v.z; Bs[k4 + 3][row] = v.w;
        }
        __syncthreads();

#pragma unroll
        for (int k = 0; k < BK; k++) {
            float ra[8], rb[8];
            *reinterpret_cast<float4*>(ra)     = *reinterpret_cast<const float4*>(&As[k][ty * 8]);
            *reinterpret_cast<float4*>(ra + 4) = *reinterpret_cast<const float4*>(&As[k][ty * 8 + 4]);
            *reinterpret_cast<float4*>(rb)     = *reinterpret_cast<const float4*>(&Bs[k][tx * 8]);
            *reinterpret_cast<float4*>(rb + 4) = *reinterpret_cast<const float4*>(&Bs[k][tx * 8 + 4]);
#pragma unroll
            for (int i = 0; i < 8; i++)
#pragma unroll
                for (int j = 0; j < 8; j++)
                    acc[i][j] = fmaf(ra[i], rb[j], acc[i][j]);
        }
        __syncthreads();
    }

    float bv[8];
#pragma unroll
    for (int j = 0; j < 8; j++) bv[j] = bias[bn + tx * 8 + j];

#pragma unroll
    for (int i = 0; i < 8; i++) {
        size_t off = (size_t)(bm + ty * 8 + i) * N + bn + tx * 8;
        float4 o0 = make_float4(acc[i][0] + bv[0], acc[i][1] + bv[1],
                                acc[i][2] + bv[2], acc[i][3] + bv[3]);
        float4 o1 = make_float4(acc[i][4] + bv[4], acc[i][5] + bv[5],
                                acc[i][6] + bv[6], acc[i][7] + bv[7]);
        *reinterpret_cast<float4*>(C + off)     = o0;
        *reinterpret_cast<float4*>(C + off + 4) = o1;
    }
}

__global__ void __launch_bounds__(256) gemm_in(
    const float* __restrict__ x, const float* __restrict__ w,
    const float* __restrict__ b)
{
    gemm_body(x, w, b, g_qkv, B_ * T_, 3 * E_, E_);
}

__global__ void __launch_bounds__(256) gemm_out(
    const float* __restrict__ w, const float* __restrict__ b)
{
    gemm_body(g_att, w, b, g_p1, B_ * T_, E_, E_);
}

__global__ void __launch_bounds__(256) gemm_c(
    const float* __restrict__ w, const float* __restrict__ b,
    float* __restrict__ out)
{
    gemm_body(g_p1, w, b, out, B_ * T_, E_, E_);
}

// ---------------------------------------------------------------------------
extern "C" void kernel_launch(void* const* d_in, const int* in_sizes, int n_in,
                              void* d_out, int out_size)
{
    const float* x  = (const float*)d_in[0];
    const float* wi = (const float*)d_in[1];
    const float* bi = (const float*)d_in[2];
    const float* wo = (const float*)d_in[3];
    const float* bo = (const float*)d_in[4];
    const float* wc = (const float*)d_in[5];
    const float* bc = (const float*)d_in[6];
    float* out = (float*)d_out;

    const int M = B_ * T_;  // 8192

    // 1) fused QKV projection: g_qkv = x @ Win^T + bin   [8192, 3072]
    gemm_in<<<dim3(3 * E_ / 128, M / 128), 256>>>(x, wi, bi);
    // 2) causal attention -> g_att [B, T, E]
    flash_attn<<<dim3(T_ / 64, B_ * H_), 256>>>();
    // 3) out_proj: g_p1 = g_att @ Wo^T + bo
    gemm_out<<<dim3(E_ / 128, M / 128), 256>>>(wo, bo);
    // 4) c_proj -> final output
    gemm_c<<<dim3(E_ / 128, M / 128), 256>>>(wc, bc, out);
}

// round 3
// speedup vs baseline: 1.9153x; 1.9153x over previous
#include <cuda_runtime.h>
#include <math.h>
#include <stdint.h>

#define B_  8
#define T_  1024
#define E_  1024
#define H_  16
#define DH_ 64

// Scratch (__device__ globals: allocation-free rule)
__device__ float g_qkv[(size_t)B_ * T_ * 3 * E_];  // 96 MB
__device__ float g_att[(size_t)B_ * T_ * E_];      // 32 MB
__device__ float g_p1 [(size_t)B_ * T_ * E_];      // 32 MB
__device__ float g_xc [(size_t)B_ * T_ * E_];      // 32 MB (tf32-rounded x)
__device__ float g_wi [(size_t)3 * E_ * E_];       // 12 MB (rounded weights)
__device__ float g_wo [(size_t)E_ * E_];
__device__ float g_wc [(size_t)E_ * E_];

// ---------------------------------------------------------------------------
// helpers
// ---------------------------------------------------------------------------
__device__ __forceinline__ float tf32r(float x) {
    uint32_t u;
    asm("cvt.rna.tf32.f32 %0, %1;" : "=r"(u) : "f"(x));
    return __uint_as_float(u);
}
__device__ __forceinline__ uint32_t sptr(const void* p) {
    return (uint32_t)__cvta_generic_to_shared(p);
}

// elementwise round-to-tf32 copy kernels --------------------------------------
__global__ void __launch_bounds__(256) cvt_x(const float* __restrict__ in) {
    int i = blockIdx.x * blockDim.x + threadIdx.x;
    const int n4 = B_ * T_ * E_ / 4;
    if (i < n4) {
        float4 v = reinterpret_cast<const float4*>(in)[i];
        v.x = tf32r(v.x); v.y = tf32r(v.y); v.z = tf32r(v.z); v.w = tf32r(v.w);
        reinterpret_cast<float4*>(g_xc)[i] = v;
    }
}
__global__ void __launch_bounds__(256) cvt_w(const float* __restrict__ wi,
                                             const float* __restrict__ wo,
                                             const float* __restrict__ wc) {
    int i = blockIdx.x * blockDim.x + threadIdx.x;
    const int n_i = 3 * E_ * E_ / 4;
    const int n_o = E_ * E_ / 4;
    const float4* src;
    float4* dst;
    int j;
    if (i < n_i)                 { src = (const float4*)wi; dst = (float4*)g_wi; j = i; }
    else if (i < n_i + n_o)      { src = (const float4*)wo; dst = (float4*)g_wo; j = i - n_i; }
    else if (i < n_i + 2 * n_o)  { src = (const float4*)wc; dst = (float4*)g_wc; j = i - n_i - n_o; }
    else return;
    float4 v = src[j];
    v.x = tf32r(v.x); v.y = tf32r(v.y); v.z = tf32r(v.z); v.w = tf32r(v.w);
    dst[j] = v;
}

// ---------------------------------------------------------------------------
// TF32 tensor-core GEMM: C[M,N] = A[M,K] @ B[N,K]^T + bias[N]
// 128x128 CTA tile, BK=16, 8 warps in 2(M)x4(N), warp tile 64x32.
// mma.sync.aligned.m16n8k8 tf32. cp.async double-buffered pipeline.
// Inputs A,B must already be tf32-rounded fp32 (HW truncation then lossless).
// M,N,K all divide tile sizes (no bounds checks).
// ---------------------------------------------------------------------------
__device__ __forceinline__ void gemm_tf32_body(
    const float* __restrict__ A, const float* __restrict__ Bm,
    const float* __restrict__ bias, float* __restrict__ C,
    int N, int K, int round_out)
{
    __shared__ float As[2][128][20];
    __shared__ float Bs[2][128][20];

    const int tid  = threadIdx.x;
    const int lane = tid & 31;
    const int wid  = tid >> 5;
    const int gid  = lane >> 2;      // 0..7
    const int tig  = lane & 3;       // 0..3
    const int wm   = (wid >> 2) * 64;
    const int wn   = (wid & 3) * 32;
    const int bm   = blockIdx.y * 128;
    const int bn   = blockIdx.x * 128;

    float acc[4][4][4];
#pragma unroll
    for (int mt = 0; mt < 4; mt++)
#pragma unroll
        for (int nt = 0; nt < 4; nt++)
#pragma unroll
            for (int r = 0; r < 4; r++) acc[mt][nt][r] = 0.f;

    auto issue = [&](int k0, int bufi) {
#pragma unroll
        for (int i = 0; i < 2; i++) {
            int idx = tid + i * 256;           // 0..511
            int row = idx >> 2;                // 0..127
            int c4  = (idx & 3) << 2;          // 0,4,8,12
            uint32_t da = sptr(&As[bufi][row][c4]);
            const float* ga = A + (size_t)(bm + row) * K + k0 + c4;
            asm volatile("cp.async.cg.shared.global [%0], [%1], 16;\n"
                         :: "r"(da), "l"(ga));
            uint32_t db = sptr(&Bs[bufi][row][c4]);
            const float* gb = Bm + (size_t)(bn + row) * K + k0 + c4;
            asm volatile("cp.async.cg.shared.global [%0], [%1], 16;\n"
                         :: "r"(db), "l"(gb));
        }
    };

    issue(0, 0);
    asm volatile("cp.async.commit_group;\n" ::: "memory");

    const int NIT = K / 16;
    for (int it = 0; it < NIT; it++) {
        if (it + 1 < NIT) {
            issue((it + 1) * 16, (it + 1) & 1);
            asm volatile("cp.async.commit_group;\n" ::: "memory");
            asm volatile("cp.async.wait_group 1;\n" ::: "memory");
        } else {
            asm volatile("cp.async.wait_group 0;\n" ::: "memory");
        }
        __syncthreads();

        const int bufi = it & 1;
#pragma unroll
        for (int ks = 0; ks < 2; ks++) {
            const int kk = ks * 8 + tig;
            uint32_t a[4][4], b[4][2];
#pragma unroll
            for (int mt = 0; mt < 4; mt++) {
                int r0 = wm + mt * 16 + gid;
                a[mt][0] = __float_as_uint(As[bufi][r0    ][kk    ]);
                a[mt][1] = __float_as_uint(As[bufi][r0 + 8][kk    ]);
                a[mt][2] = __float_as_uint(As[bufi][r0    ][kk + 4]);
                a[mt][3] = __float_as_uint(As[bufi][r0 + 8][kk + 4]);
            }
#pragma unroll
            for (int nt = 0; nt < 4; nt++) {
                int c0i = wn + nt * 8 + gid;
                b[nt][0] = __float_as_uint(Bs[bufi][c0i][kk    ]);
                b[nt][1] = __float_as_uint(Bs[bufi][c0i][kk + 4]);
            }
#pragma unroll
            for (int mt = 0; mt < 4; mt++)
#pragma unroll
                for (int nt = 0; nt < 4; nt++)
                    asm volatile(
                        "mma.sync.aligned.m16n8k8.row.col.f32.tf32.tf32.f32 "
                        "{%0,%1,%2,%3},{%4,%5,%6,%7},{%8,%9},{%0,%1,%2,%3};"
                        : "+f"(acc[mt][nt][0]), "+f"(acc[mt][nt][1]),
                          "+f"(acc[mt][nt][2]), "+f"(acc[mt][nt][3])
                        : "r"(a[mt][0]), "r"(a[mt][1]), "r"(a[mt][2]), "r"(a[mt][3]),
                          "r"(b[nt][0]), "r"(b[nt][1]));
        }
        __syncthreads();
    }

    // epilogue: bias add (+ optional tf32 rounding for next GEMM's consumption)
#pragma unroll
    for (int mt = 0; mt < 4; mt++) {
#pragma unroll
        for (int nt = 0; nt < 4; nt++) {
            int row = bm + wm + mt * 16 + gid;
            int col = bn + wn + nt * 8 + tig * 2;
            float bv0 = bias[col], bv1 = bias[col + 1];
            float v0 = acc[mt][nt][0] + bv0;
            float v1 = acc[mt][nt][1] + bv1;
            float v2 = acc[mt][nt][2] + bv0;
            float v3 = acc[mt][nt][3] + bv1;
            if (round_out) {
                v0 = tf32r(v0); v1 = tf32r(v1); v2 = tf32r(v2); v3 = tf32r(v3);
            }
            *reinterpret_cast<float2*>(C + (size_t)row * N + col) = make_float2(v0, v1);
            *reinterpret_cast<float2*>(C + (size_t)(row + 8) * N + col) = make_float2(v2, v3);
        }
    }
}

__global__ void __launch_bounds__(256, 2) gemm_in_k(const float* __restrict__ bi) {
    gemm_tf32_body(g_xc, g_wi, bi, g_qkv, 3 * E_, E_, 0);
}
__global__ void __launch_bounds__(256, 2) gemm_out_k(const float* __restrict__ bo) {
    gemm_tf32_body(g_att, g_wo, bo, g_p1, E_, E_, 1);
}
__global__ void __launch_bounds__(256, 2) gemm_c_k(const float* __restrict__ bc,
                                                   float* __restrict__ out) {
    gemm_tf32_body(g_p1, g_wc, bc, out, E_, E_, 0);
}

// ---------------------------------------------------------------------------
// Causal flash attention, fp32 (unchanged math; epilogue rounds output to
// tf32 so the following GEMM's HW truncation is lossless).
// grid: (T/64, B*H). 256 threads. 64 query rows per CTA, KV tiles of 32.
// ---------------------------------------------------------------------------
__global__ void __launch_bounds__(256) flash_attn()
{
    __shared__ float Qs[64][68];
    __shared__ float Ks[64][36];
    __shared__ float Vs[32][68];
    __shared__ float Ps[32][68];

    const float* qkv = g_qkv;
    float* out = g_att;

    const int tid = threadIdx.x;
    const int tx  = tid & 15;
    const int ty  = tid >> 4;
    const int qb  = blockIdx.x;
    const int b   = blockIdx.y >> 4;
    const int h   = blockIdx.y & 15;
    const size_t base = (size_t)b * T_ * 3 * E_ + (size_t)h * DH_;

#pragma unroll
    for (int i = 0; i < 4; i++) {
        int idx = tid + i * 256;
        int row = idx >> 4;
        int d4  = (idx & 15) << 2;
        float4 v = *reinterpret_cast<const float4*>(
            qkv + base + (size_t)(qb * 64 + row) * 3 * E_ + d4);
        Qs[d4 + 0][row] = v.x; Qs[d4 + 1][row] = v.y;
        Qs[d4 + 2][row] = v.z; Qs[d4 + 3][row] = v.w;
    }

    float m[4], l[4], o[4][4];
#pragma unroll
    for (int i = 0; i < 4; i++) {
        m[i] = -INFINITY; l[i] = 0.f;
#pragma unroll
        for (int j = 0; j < 4; j++) o[i][j] = 0.f;
    }

    const int nkb = 2 * qb + 2;
    for (int kb = 0; kb < nkb; kb++) {
        __syncthreads();
#pragma unroll
        for (int i = 0; i < 2; i++) {
            int idx = tid + i * 256;
            int row = idx >> 4;
            int d4  = (idx & 15) << 2;
            size_t tok = (size_t)(kb * 32 + row) * 3 * E_;
            float4 kv4 = *reinterpret_cast<const float4*>(qkv + base + E_ + tok + d4);
            Ks[d4 + 0][row] = kv4.x; Ks[d4 + 1][row] = kv4.y;
            Ks[d4 + 2][row] = kv4.z; Ks[d4 + 3][row] = kv4.w;
            *reinterpret_cast<float4*>(&Vs[row][d4]) =
                *reinterpret_cast<const float4*>(qkv + base + 2 * E_ + tok + d4);
        }
        __syncthreads();

        float s[4][2] = {};
#pragma unroll 16
        for (int d = 0; d < 64; d++) {
            float4 qa = *reinterpret_cast<const float4*>(&Qs[d][ty * 4]);
            float k0 = Ks[d][tx * 2], k1 = Ks[d][tx * 2 + 1];
            s[0][0] = fmaf(qa.x, k0, s[0][0]); s[0][1] = fmaf(qa.x, k1, s[0][1]);
            s[1][0] = fmaf(qa.y, k0, s[1][0]); s[1][1] = fmaf(qa.y, k1, s[1][1]);
            s[2][0] = fmaf(qa.z, k0, s[2][0]); s[2][1] = fmaf(qa.z, k1, s[2][1]);
            s[3][0] = fmaf(qa.w, k0, s[3][0]); s[3][1] = fmaf(qa.w, k1, s[3][1]);
        }

        const bool need_mask = (kb >= 2 * qb);
#pragma unroll
        for (int i = 0; i < 4; i++)
#pragma unroll
            for (int j = 0; j < 2; j++) {
                float sv = s[i][j] * 0.125f;
                if (need_mask) {
                    int rg = qb * 64 + ty * 4 + i;
                    int cg = kb * 32 + tx * 2 + j;
                    if (cg > rg) sv = -1e30f;
                }
                s[i][j] = sv;
            }

#pragma unroll
        for (int i = 0; i < 4; i++) {
            float rm = fmaxf(s[i][0], s[i][1]);
#pragma unroll
            for (int ofs = 8; ofs > 0; ofs >>= 1)
                rm = fmaxf(rm, __shfl_xor_sync(0xffffffffu, rm, ofs));
            float mn = fmaxf(m[i], rm);
            float alpha = __expf(m[i] - mn);
            m[i] = mn;
            float p0 = __expf(s[i][0] - mn);
            float p1 = __expf(s[i][1] - mn);
            float rs = p0 + p1;
#pragma unroll
            for (int ofs = 8; ofs > 0; ofs >>= 1)
                rs += __shfl_xor_sync(0xffffffffu, rs, ofs);
            l[i] = l[i] * alpha + rs;
#pragma unroll
            for (int j = 0; j < 4; j++) o[i][j] *= alpha;
            Ps[tx * 2 + 0][ty * 4 + i] = p0;
            Ps[tx * 2 + 1][ty * 4 + i] = p1;
        }
        __syncthreads();

#pragma unroll 8
        for (int c = 0; c < 32; c++) {
            float4 vv = *reinterpret_cast<const float4*>(&Vs[c][tx * 4]);
#pragma unroll
            for (int i = 0; i < 4; i++) {
                float p = Ps[c][ty * 4 + i];
                o[i][0] = fmaf(p, vv.x, o[i][0]);
                o[i][1] = fmaf(p, vv.y, o[i][1]);
                o[i][2] = fmaf(p, vv.z, o[i][2]);
                o[i][3] = fmaf(p, vv.w, o[i][3]);
            }
        }
    }

#pragma unroll
    for (int i = 0; i < 4; i++) {
        float inv = 1.f / l[i];
        size_t off = ((size_t)b * T_ + qb * 64 + ty * 4 + i) * E_ + h * DH_ + tx * 4;
        float4 ov = make_float4(tf32r(o[i][0] * inv), tf32r(o[i][1] * inv),
                                tf32r(o[i][2] * inv), tf32r(o[i][3] * inv));
        *reinterpret_cast<float4*>(out + off) = ov;
    }
}

// ---------------------------------------------------------------------------
extern "C" void kernel_launch(void* const* d_in, const int* in_sizes, int n_in,
                              void* d_out, int out_size)
{
    const float* x  = (const float*)d_in[0];
    const float* wi = (const float*)d_in[1];
    const float* bi = (const float*)d_in[2];
    const float* wo = (const float*)d_in[3];
    const float* bo = (const float*)d_in[4];
    const float* wc = (const float*)d_in[5];
    const float* bc = (const float*)d_in[6];
    float* out = (float*)d_out;

    const int M = B_ * T_;  // 8192

    // 0) round inputs/weights to tf32 grid (rna, unbiased)
    cvt_x<<<(B_ * T_ * E_ / 4 + 255) / 256, 256>>>(x);
    cvt_w<<<(5 * E_ * E_ / 4 + 255) / 256, 256>>>(wi, wo, wc);
    // 1) fused QKV projection: g_qkv = xc @ wi^T + bi   [8192, 3072]
    gemm_in_k<<<dim3(3 * E_ / 128, M / 128), 256>>>(bi);
    // 2) causal attention -> g_att [B, T, E] (tf32-rounded)
    flash_attn<<<dim3(T_ / 64, B_ * H_), 256>>>();
    // 3) out_proj: g_p1 = att @ wo^T + bo (tf32-rounded)
    gemm_out_k<<<dim3(E_ / 128, M / 128), 256>>>(bo);
    // 4) c_proj -> final output (full fp32)
    gemm_c_k<<<dim3(E_ / 128, M / 128), 256>>>(bc, out);
}

// round 5
// speedup vs baseline: 2.7980x; 1.4609x over previous
#include <cuda_runtime.h>
#include <math.h>
#include <stdint.h>

#define B_  8
#define T_  1024
#define E_  1024
#define H_  16
#define DH_ 64

// Scratch (__device__ globals: allocation-free rule)
__device__ float g_qkv[(size_t)B_ * T_ * 3 * E_];  // 96 MB
__device__ float g_att[(size_t)B_ * T_ * E_];      // 32 MB
__device__ float g_p1 [(size_t)B_ * T_ * E_];      // 32 MB
__device__ float g_xc [(size_t)B_ * T_ * E_];      // 32 MB (tf32-rounded x)
__device__ float g_wi [(size_t)3 * E_ * E_];       // 12 MB (rounded weights)
__device__ float g_wo [(size_t)E_ * E_];
__device__ float g_wc [(size_t)E_ * E_];

// ---------------------------------------------------------------------------
__device__ __forceinline__ float tf32r(float x) {
    uint32_t u;
    asm("cvt.rna.tf32.f32 %0, %1;" : "=r"(u) : "f"(x));
    return __uint_as_float(u);
}
__device__ __forceinline__ uint32_t sptr(const void* p) {
    return (uint32_t)__cvta_generic_to_shared(p);
}
__device__ __forceinline__ void mma_tf32(
    float& c0, float& c1, float& c2, float& c3,
    uint32_t a0, uint32_t a1, uint32_t a2, uint32_t a3,
    uint32_t b0, uint32_t b1)
{
    asm volatile(
        "mma.sync.aligned.m16n8k8.row.col.f32.tf32.tf32.f32 "
        "{%0,%1,%2,%3},{%4,%5,%6,%7},{%8,%9},{%0,%1,%2,%3};"
        : "+f"(c0), "+f"(c1), "+f"(c2), "+f"(c3)
        : "r"(a0), "r"(a1), "r"(a2), "r"(a3), "r"(b0), "r"(b1));
}

// elementwise round-to-tf32 copy kernels --------------------------------------
__global__ void __launch_bounds__(256) cvt_x(const float* __restrict__ in) {
    int i = blockIdx.x * blockDim.x + threadIdx.x;
    const int n4 = B_ * T_ * E_ / 4;
    if (i < n4) {
        float4 v = reinterpret_cast<const float4*>(in)[i];
        v.x = tf32r(v.x); v.y = tf32r(v.y); v.z = tf32r(v.z); v.w = tf32r(v.w);
        reinterpret_cast<float4*>(g_xc)[i] = v;
    }
}
__global__ void __launch_bounds__(256) cvt_w(const float* __restrict__ wi,
                                             const float* __restrict__ wo,
                                             const float* __restrict__ wc) {
    int i = blockIdx.x * blockDim.x + threadIdx.x;
    const int n_i = 3 * E_ * E_ / 4;
    const int n_o = E_ * E_ / 4;
    const float4* src;
    float4* dst;
    int j;
    if (i < n_i)                 { src = (const float4*)wi; dst = (float4*)g_wi; j = i; }
    else if (i < n_i + n_o)      { src = (const float4*)wo; dst = (float4*)g_wo; j = i - n_i; }
    else if (i < n_i + 2 * n_o)  { src = (const float4*)wc; dst = (float4*)g_wc; j = i - n_i - n_o; }
    else return;
    float4 v = src[j];
    v.x = tf32r(v.x); v.y = tf32r(v.y); v.z = tf32r(v.z); v.w = tf32r(v.w);
    dst[j] = v;
}

// ---------------------------------------------------------------------------
// TF32 tensor-core GEMM: C[M,N] = A[M,K] @ B[N,K]^T + bias[N]
// 128x128 CTA tile, BK=16, 8 warps 2x4, warp tile 64x32, cp.async 2-stage.
// ---------------------------------------------------------------------------
__device__ __forceinline__ void gemm_tf32_body(
    const float* __restrict__ A, const float* __restrict__ Bm,
    const float* __restrict__ bias, float* __restrict__ C,
    int N, int K, int round_out)
{
    __shared__ float As[2][128][20];
    __shared__ float Bs[2][128][20];

    const int tid  = threadIdx.x;
    const int lane = tid & 31;
    const int wid  = tid >> 5;
    const int gid  = lane >> 2;
    const int tig  = lane & 3;
    const int wm   = (wid >> 2) * 64;
    const int wn   = (wid & 3) * 32;
    const int bm   = blockIdx.y * 128;
    const int bn   = blockIdx.x * 128;

    float acc[4][4][4];
#pragma unroll
    for (int mt = 0; mt < 4; mt++)
#pragma unroll
        for (int nt = 0; nt < 4; nt++)
#pragma unroll
            for (int r = 0; r < 4; r++) acc[mt][nt][r] = 0.f;

    auto issue = [&](int k0, int bufi) {
#pragma unroll
        for (int i = 0; i < 2; i++) {
            int idx = tid + i * 256;
            int row = idx >> 2;
            int c4  = (idx & 3) << 2;
            uint32_t da = sptr(&As[bufi][row][c4]);
            const float* ga = A + (size_t)(bm + row) * K + k0 + c4;
            asm volatile("cp.async.cg.shared.global [%0], [%1], 16;\n" :: "r"(da), "l"(ga));
            uint32_t db = sptr(&Bs[bufi][row][c4]);
            const float* gb = Bm + (size_t)(bn + row) * K + k0 + c4;
            asm volatile("cp.async.cg.shared.global [%0], [%1], 16;\n" :: "r"(db), "l"(gb));
        }
    };

    issue(0, 0);
    asm volatile("cp.async.commit_group;\n" ::: "memory");

    const int NIT = K / 16;
    for (int it = 0; it < NIT; it++) {
        if (it + 1 < NIT) {
            issue((it + 1) * 16, (it + 1) & 1);
            asm volatile("cp.async.commit_group;\n" ::: "memory");
            asm volatile("cp.async.wait_group 1;\n" ::: "memory");
        } else {
            asm volatile("cp.async.wait_group 0;\n" ::: "memory");
        }
        __syncthreads();

        const int bufi = it & 1;
#pragma unroll
        for (int ks = 0; ks < 2; ks++) {
            const int kk = ks * 8 + tig;
            uint32_t a[4][4], b[4][2];
#pragma unroll
            for (int mt = 0; mt < 4; mt++) {
                int r0 = wm + mt * 16 + gid;
                a[mt][0] = __float_as_uint(As[bufi][r0    ][kk    ]);
                a[mt][1] = __float_as_uint(As[bufi][r0 + 8][kk    ]);
                a[mt][2] = __float_as_uint(As[bufi][r0    ][kk + 4]);
                a[mt][3] = __float_as_uint(As[bufi][r0 + 8][kk + 4]);
            }
#pragma unroll
            for (int nt = 0; nt < 4; nt++) {
                int c0i = wn + nt * 8 + gid;
                b[nt][0] = __float_as_uint(Bs[bufi][c0i][kk    ]);
                b[nt][1] = __float_as_uint(Bs[bufi][c0i][kk + 4]);
            }
#pragma unroll
            for (int mt = 0; mt < 4; mt++)
#pragma unroll
                for (int nt = 0; nt < 4; nt++)
                    mma_tf32(acc[mt][nt][0], acc[mt][nt][1], acc[mt][nt][2], acc[mt][nt][3],
                             a[mt][0], a[mt][1], a[mt][2], a[mt][3], b[nt][0], b[nt][1]);
        }
        __syncthreads();
    }

#pragma unroll
    for (int mt = 0; mt < 4; mt++) {
#pragma unroll
        for (int nt = 0; nt < 4; nt++) {
            int row = bm + wm + mt * 16 + gid;
            int col = bn + wn + nt * 8 + tig * 2;
            float bv0 = bias[col], bv1 = bias[col + 1];
            float v0 = acc[mt][nt][0] + bv0;
            float v1 = acc[mt][nt][1] + bv1;
            float v2 = acc[mt][nt][2] + bv0;
            float v3 = acc[mt][nt][3] + bv1;
            if (round_out) {
                v0 = tf32r(v0); v1 = tf32r(v1); v2 = tf32r(v2); v3 = tf32r(v3);
            }
            *reinterpret_cast<float2*>(C + (size_t)row * N + col) = make_float2(v0, v1);
            *reinterpret_cast<float2*>(C + (size_t)(row + 8) * N + col) = make_float2(v2, v3);
        }
    }
}

__global__ void __launch_bounds__(256, 2) gemm_in_k(const float* __restrict__ bi) {
    gemm_tf32_body(g_xc, g_wi, bi, g_qkv, 3 * E_, E_, 1);   // round: attention consumes via MMA
}
__global__ void __launch_bounds__(256, 2) gemm_out_k(const float* __restrict__ bo) {
    gemm_tf32_body(g_att, g_wo, bo, g_p1, E_, E_, 1);
}
__global__ void __launch_bounds__(256, 2) gemm_c_k(const float* __restrict__ bc,
                                                   float* __restrict__ out) {
    gemm_tf32_body(g_p1, g_wc, bc, out, E_, E_, 0);
}

// ---------------------------------------------------------------------------
// Tensor-core causal flash attention (tf32 MMA, fp32 softmax).
// grid (T/64, B*H), 128 threads (4 warps), warp = 16 query rows.
// KV tile = 64. K smem [key][d-interleaved], V smem transposed [d][key-ilv].
// V columns additionally XOR-swizzled by f(d)=((d>>2)&3)<<1 to cut the
// transpose-store bank conflict from 16-way to 4-way; reads apply the same
// XOR (f even -> float2 pair stays contiguous, keys (tig, tig+4) preserved).
// ---------------------------------------------------------------------------
#define ST_ 72
__device__ __forceinline__ int ilv8(int o) {   // 0..7 -> 0,2,4,6,1,3,5,7
    return ((o & 3) << 1) | ((o >> 2) & 1);
}

__global__ void __launch_bounds__(128, 3) flash_attn()
{
    __shared__ __align__(16) float sm0[64 * ST_];  // Q, then K tiles
    __shared__ __align__(16) float sm1[64 * ST_];  // V^T tiles

    const float* qkv = g_qkv;
    const int tid  = threadIdx.x;
    const int lane = tid & 31;
    const int w    = tid >> 5;
    const int gid  = lane >> 2;
    const int tig  = lane & 3;
    const int qb   = blockIdx.x;
    const int b    = blockIdx.y >> 4;
    const int h    = blockIdx.y & 15;
    const size_t base = (size_t)b * T_ * 3 * E_ + (size_t)h * DH_;

    // ---- load Q tile (64x64) into sm0, d-interleaved ----
#pragma unroll
    for (int i = 0; i < 8; i++) {
        int idx = tid + i * 128;              // 0..1023
        int row = idx >> 4;
        int d4  = (idx & 15) << 2;
        float4 v = *reinterpret_cast<const float4*>(
            qkv + base + (size_t)(qb * 64 + row) * 3 * E_ + d4);
        int bp = (d4 & ~7) | ((d4 >> 2) & 1);
        sm0[row * ST_ + bp    ] = v.x;
        sm0[row * ST_ + bp + 2] = v.y;
        sm0[row * ST_ + bp + 4] = v.z;
        sm0[row * ST_ + bp + 6] = v.w;
    }
    __syncthreads();

    // ---- Q fragments to registers (scale 1/8 folded: exact pow2) ----
    uint32_t qf[8][4];
    {
        const int r0 = w * 16 + gid;
#pragma unroll
        for (int kc = 0; kc < 8; kc++) {
            float2 t0 = *reinterpret_cast<const float2*>(&sm0[ r0      * ST_ + kc * 8 + 2 * tig]);
            float2 t1 = *reinterpret_cast<const float2*>(&sm0[(r0 + 8) * ST_ + kc * 8 + 2 * tig]);
            qf[kc][0] = __float_as_uint(t0.x * 0.125f);
            qf[kc][1] = __float_as_uint(t1.x * 0.125f);
            qf[kc][2] = __float_as_uint(t0.y * 0.125f);
            qf[kc][3] = __float_as_uint(t1.y * 0.125f);
        }
    }

    float m0 = -1e30f, m1 = -1e30f, l0 = 0.f, l1 = 0.f;
    float oacc[8][4];
#pragma unroll
    for (int n = 0; n < 8; n++)
#pragma unroll
        for (int r = 0; r < 4; r++) oacc[n][r] = 0.f;

    const int nkb = qb + 1;
    for (int kb = 0; kb < nkb; kb++) {
        __syncthreads();   // prior iter (or Q frag reads) done with sm0/sm1

        // ---- load K (direct, d-interleaved) and V (transposed, swizzled) ----
#pragma unroll
        for (int i = 0; i < 8; i++) {
            int idx = tid + i * 128;
            int row = idx >> 4;               // key 0..63
            int d4  = (idx & 15) << 2;
            size_t tok = (size_t)(kb * 64 + row) * 3 * E_;
            float4 kv4 = *reinterpret_cast<const float4*>(qkv + base + E_ + tok + d4);
            int bp = (d4 & ~7) | ((d4 >> 2) & 1);
            sm0[row * ST_ + bp    ] = kv4.x;
            sm0[row * ST_ + bp + 2] = kv4.y;
            sm0[row * ST_ + bp + 4] = kv4.z;
            sm0[row * ST_ + bp + 6] = kv4.w;
            float4 vv4 = *reinterpret_cast<const float4*>(qkv + base + 2 * E_ + tok + d4);
            int f  = ((d4 >> 2) & 3) << 1;    // same for d4..d4+3
            int pk = (row & ~7) | (ilv8(row & 7) ^ f);
            sm1[(d4 + 0) * ST_ + pk] = vv4.x;
            sm1[(d4 + 1) * ST_ + pk] = vv4.y;
            sm1[(d4 + 2) * ST_ + pk] = vv4.z;
            sm1[(d4 + 3) * ST_ + pk] = vv4.w;
        }
        __syncthreads();

        // ---- S = Q K^T : 8 n-tiles (keys) x 8 k-steps (d) ----
        float sacc[8][4];
#pragma unroll
        for (int n = 0; n < 8; n++)
#pragma unroll
            for (int r = 0; r < 4; r++) sacc[n][r] = 0.f;

#pragma unroll
        for (int kc = 0; kc < 8; kc++)
#pragma unroll
            for (int n = 0; n < 8; n++) {
                float2 bb = *reinterpret_cast<const float2*>(
                    &sm0[(n * 8 + gid) * ST_ + kc * 8 + 2 * tig]);
                mma_tf32(sacc[n][0], sacc[n][1], sacc[n][2], sacc[n][3],
                         qf[kc][0], qf[kc][1], qf[kc][2], qf[kc][3],
                         __float_as_uint(bb.x), __float_as_uint(bb.y));
            }

        // ---- causal mask (diagonal tile only) ----
        if (kb == qb) {
            const int r0 = w * 16 + gid;
#pragma unroll
            for (int n = 0; n < 8; n++) {
                int c = n * 8 + 2 * tig;
                if (c     > r0    ) sacc[n][0] = -1e30f;
                if (c + 1 > r0    ) sacc[n][1] = -1e30f;
                if (c     > r0 + 8) sacc[n][2] = -1e30f;
                if (c + 1 > r0 + 8) sacc[n][3] = -1e30f;
            }
        }

        // ---- online softmax (rows gid / gid+8), reduce over quad lanes ----
        float mx0 = -1e30f, mx1 = -1e30f;
#pragma unroll
        for (int n = 0; n < 8; n++) {
            mx0 = fmaxf(mx0, fmaxf(sacc[n][0], sacc[n][1]));
            mx1 = fmaxf(mx1, fmaxf(sacc[n][2], sacc[n][3]));
        }
        mx0 = fmaxf(mx0, __shfl_xor_sync(0xffffffffu, mx0, 1));
        mx0 = fmaxf(mx0, __shfl_xor_sync(0xffffffffu, mx0, 2));
        mx1 = fmaxf(mx1, __shfl_xor_sync(0xffffffffu, mx1, 1));
        mx1 = fmaxf(mx1, __shfl_xor_sync(0xffffffffu, mx1, 2));
        float mn0 = fmaxf(m0, mx0), mn1 = fmaxf(m1, mx1);
        float al0 = __expf(m0 - mn0), al1 = __expf(m1 - mn1);
        m0 = mn0; m1 = mn1;

        float sum0 = 0.f, sum1 = 0.f;
#pragma unroll
        for (int n = 0; n < 8; n++) {
            float p0 = tf32r(__expf(sacc[n][0] - mn0));
            float p1 = tf32r(__expf(sacc[n][1] - mn0));
            float p2 = tf32r(__expf(sacc[n][2] - mn1));
            float p3 = tf32r(__expf(sacc[n][3] - mn1));
            sum0 += p0 + p1; sum1 += p2 + p3;
            sacc[n][0] = p0; sacc[n][1] = p1; sacc[n][2] = p2; sacc[n][3] = p3;
        }
        sum0 += __shfl_xor_sync(0xffffffffu, sum0, 1);
        sum0 += __shfl_xor_sync(0xffffffffu, sum0, 2);
        sum1 += __shfl_xor_sync(0xffffffffu, sum1, 1);
        sum1 += __shfl_xor_sync(0xffffffffu, sum1, 2);
        l0 = l0 * al0 + sum0;
        l1 = l1 * al1 + sum1;
#pragma unroll
        for (int n = 0; n < 8; n++) {
            oacc[n][0] *= al0; oacc[n][1] *= al0;
            oacc[n][2] *= al1; oacc[n][3] *= al1;
        }

        // ---- O += P V : shuffle P C-frags -> A-frags, 8 k-chunks ----
        const int src0 = (lane & 28) | (tig >> 1);
        const int src1 = src0 + 2;
        const bool odd = (tig & 1);
#pragma unroll
        for (int kc = 0; kc < 8; kc++) {
            float v00 = __shfl_sync(0xffffffffu, sacc[kc][0], src0);
            float v01 = __shfl_sync(0xffffffffu, sacc[kc][1], src0);
            float v10 = __shfl_sync(0xffffffffu, sacc[kc][0], src1);
            float v11 = __shfl_sync(0xffffffffu, sacc[kc][1], src1);
            float v20 = __shfl_sync(0xffffffffu, sacc[kc][2], src0);
            float v21 = __shfl_sync(0xffffffffu, sacc[kc][3], src0);
            float v30 = __shfl_sync(0xffffffffu, sacc[kc][2], src1);
            float v31 = __shfl_sync(0xffffffffu, sacc[kc][3], src1);
            uint32_t a0 = __float_as_uint(odd ? v01 : v00);
            uint32_t a2 = __float_as_uint(odd ? v11 : v10);
            uint32_t a1 = __float_as_uint(odd ? v21 : v20);
            uint32_t a3 = __float_as_uint(odd ? v31 : v30);
#pragma unroll
            for (int n = 0; n < 8; n++) {
                int rowd = n * 8 + gid;
                int f    = ((rowd >> 2) & 3) << 1;
                float2 vb = *reinterpret_cast<const float2*>(
                    &sm1[rowd * ST_ + kc * 8 + ((2 * tig) ^ f)]);
                mma_tf32(oacc[n][0], oacc[n][1], oacc[n][2], oacc[n][3],
                         a0, a1, a2, a3,
                         __float_as_uint(vb.x), __float_as_uint(vb.y));
            }
        }
    }

    // ---- epilogue: normalize, round to tf32 grid, write [B,T,E] ----
    const float inv0 = 1.f / l0, inv1 = 1.f / l1;
    const int row0 = qb * 64 + w * 16 + gid;
#pragma unroll
    for (int n = 0; n < 8; n++) {
        int col = h * DH_ + n * 8 + 2 * tig;
        size_t o0 = ((size_t)b * T_ + row0) * E_ + col;
        size_t o1 = ((size_t)b * T_ + row0 + 8) * E_ + col;
        *reinterpret_cast<float2*>(g_att + o0) =
            make_float2(tf32r(oacc[n][0] * inv0), tf32r(oacc[n][1] * inv0));
        *reinterpret_cast<float2*>(g_att + o1) =
            make_float2(tf32r(oacc[n][2] * inv1), tf32r(oacc[n][3] * inv1));
    }
}

// ---------------------------------------------------------------------------
extern "C" void kernel_launch(void* const* d_in, const int* in_sizes, int n_in,
                              void* d_out, int out_size)
{
    const float* x  = (const float*)d_in[0];
    const float* wi = (const float*)d_in[1];
    const float* bi = (const float*)d_in[2];
    const float* wo = (const float*)d_in[3];
    const float* bo = (const float*)d_in[4];
    const float* wc = (const float*)d_in[5];
    const float* bc = (const float*)d_in[6];
    float* out = (float*)d_out;

    const int M = B_ * T_;  // 8192

    cvt_x<<<(B_ * T_ * E_ / 4 + 255) / 256, 256>>>(x);
    cvt_w<<<(5 * E_ * E_ / 4 + 255) / 256, 256>>>(wi, wo, wc);
    gemm_in_k<<<dim3(3 * E_ / 128, M / 128), 256>>>(bi);
    flash_attn<<<dim3(T_ / 64, B_ * H_), 128>>>();
    gemm_out_k<<<dim3(E_ / 128, M / 128), 256>>>(bo);
    gemm_c_k<<<dim3(E_ / 128, M / 128), 256>>>(bc, out);
}